// round 14
// baseline (speedup 1.0000x reference)
#include <cuda_runtime.h>
#include <cuda_fp16.h>
#include <cstdint>

// ---------------------------------------------------------------------------
// EGNN layer: N=20000 nodes, E=320000 edges, H=256.
// Round 14: exact R12 base (fp16 m16n8k16, ET=64, 2Mx8N, 2 CTA/SM, 527us)
// with A-operand loads switched from 8x LDS.32 to 2x ldmatrix.m8n8.x4 per
// k16-step (conflict-free: row stride 132 words == 4 mod 32).
// ---------------------------------------------------------------------------

#define HDIM    256
#define NNODE   20000
#define NEDGE   320000
#define LN_EPS  1e-5f

#define ET      64           // rows per MMA block
#define ETHR    512          // threads (16 warps: 2M x 8N)

// smem layout: float region then half region
#define O_F     0            // s_f [64][260] floats (edge exact staging)
#define O_ROW   16640        // 64 int
#define O_COL   16704        // 64 int
#define O_DIST  16768        // 64 f
#define O_DIFF  16832        // 192 f
#define O_RED   17024        // 64*8 f
// node aliases (same region)
#define O_R1    16640        // 512 f
#define O_R2    17152        // 512 f
#define O_MU    17664        // 64 f
#define O_RS    17728        // 64 f
#define O_H     17792        // float index where half buffer starts
#define MMA_SMEM (17792 * 4 + 64 * 264 * 2)   // 104960 B

__device__ float g_msg[NNODE * HDIM];
__device__ float g_P[NNODE * HDIM];
__device__ float g_Q[NNODE * HDIM];
__device__ float g_coord[NNODE * 3];
// fragment-packed fp16 weights: tile(nb,kt) = 128 halves, per-lane uint2
__device__ __half g_W2t[HDIM * HDIM];
__device__ __half g_C1t[HDIM * HDIM];
__device__ __half g_W1at[HDIM * HDIM];
__device__ __half g_W1bt[HDIM * HDIM];
__device__ __half g_NW1t[HDIM * 2 * HDIM];   // K = 512 (KB16 = 32)
__device__ __half g_NW2t[HDIM * HDIM];
__device__ int   g_is64;

__device__ __forceinline__ float silu_f(float v) {
    return v / (1.0f + __expf(-v));
}
__device__ __forceinline__ uint32_t smem_u32(const void* p) {
    uint32_t a;
    asm("{ .reg .u64 t; cvta.to.shared.u64 t, %1; cvt.u32.u64 %0, t; }"
        : "=r"(a) : "l"(p));
    return a;
}

#define MMA_F16(D, A0, A1, A2, A3, B0, B1)                                    \
    asm volatile(                                                             \
        "mma.sync.aligned.m16n8k16.row.col.f32.f16.f16.f32 "                  \
        "{%0,%1,%2,%3}, {%4,%5,%6,%7}, {%8,%9}, {%0,%1,%2,%3};"               \
        : "+f"((D)[0]), "+f"((D)[1]), "+f"((D)[2]), "+f"((D)[3])              \
        : "r"(A0), "r"(A1), "r"(A2), "r"(A3), "r"(B0), "r"(B1))

#define LDSM_X4(R0, R1, R2, R3, ADDR)                                         \
    asm volatile(                                                             \
        "ldmatrix.sync.aligned.m8n8.x4.shared.b16 {%0,%1,%2,%3}, [%4];"       \
        : "=r"(R0), "=r"(R1), "=r"(R2), "=r"(R3) : "r"(ADDR))

// ---------------------------------------------------------------------------
__global__ void detect_kernel(const unsigned* __restrict__ w) {
    unsigned acc = 0;
    for (int i = threadIdx.x; i < 1024; i += 32) acc |= w[2 * i + 1];
    #pragma unroll
    for (int o = 16; o; o >>= 1) acc |= __shfl_xor_sync(0xFFFFFFFFu, acc, o);
    if (threadIdx.x == 0) g_is64 = (acc == 0) ? 1 : 0;
}

__global__ void zero_kernel() {
    int i = blockIdx.x * blockDim.x + threadIdx.x;
    int stride = gridDim.x * blockDim.x;
    for (int idx = i; idx < NNODE * HDIM; idx += stride) g_msg[idx] = 0.0f;
    for (int idx = i; idx < NNODE * 3;    idx += stride) g_coord[idx] = 0.0f;
}

// transpose + fp16-round + fragment-pack all weight matrices (R12 layout).
// (n,k) of W^T -> tile (n>>3, k>>4)*128 halves +
//   ((n&7)*4 + ((k&7)>>1))*4 + ((k>>3)&1)*2 + (k&1)
__global__ void transpose_kernel(const float* __restrict__ W2,
                                 const float* __restrict__ C1,
                                 const float* __restrict__ EW1,
                                 const float* __restrict__ NW1,
                                 const float* __restrict__ NW2) {
    __shared__ float t[32][33];
    const float* src; __half* dst; int kdim = HDIM; int doff = 0;
    switch (blockIdx.z) {
        case 0: src = W2;                dst = g_W2t;  break;
        case 1: src = C1;                dst = g_C1t;  break;
        case 2: src = EW1;               dst = g_W1at; break;
        case 3: src = EW1 + HDIM * HDIM; dst = g_W1bt; break;
        case 4: src = NW1;               dst = g_NW1t; kdim = 2 * HDIM; break;
        default: src = NW1 + HDIM * HDIM; dst = g_NW1t; kdim = 2 * HDIM; doff = HDIM; break;
        case 6: src = NW2;               dst = g_NW2t; break;
    }
    int bx = blockIdx.x * 32, by = blockIdx.y * 32;
    int tx = threadIdx.x, ty = threadIdx.y;
    #pragma unroll
    for (int i = 0; i < 32; i += 8)
        t[ty + i][tx] = src[(by + ty + i) * HDIM + bx + tx];
    __syncthreads();
    int KB16 = kdim >> 4;
    #pragma unroll
    for (int i = 0; i < 32; i += 8) {
        int n = bx + ty + i;
        int k = doff + by + tx;
        int off = ((n >> 3) * KB16 + (k >> 4)) * 128
                + ((n & 7) * 4 + ((k & 7) >> 1)) * 4
                + ((k >> 3) & 1) * 2 + (k & 1);
        dst[off] = __float2half_rn(t[tx][ty + i]);
    }
}

// ---------------------------------------------------------------------------
// fp16 warp-MMA GEMM: D[64 x 256] += s_h[64 x 256k] @ W^T. Warp tile 32r x
// 32c (2 mt x 4 nt). Per k16-step: 2 LDSM.x4 (A) + 4 LDG.64 (B) + 8 MMA.
// ---------------------------------------------------------------------------
__device__ __forceinline__ void run_gemm(const __half* __restrict__ Wp,
                                         int KB16, int kb0,
                                         const __half* s_h, float d[8][4],
                                         int m0, int nb0,
                                         int g, int tig, int lane)
{
    // ldmatrix lane->address: row = m0 + (lane&15) [+16 for mt1],
    // col = (lane>>4)*8 within the k16 tile.
    uint32_t aptr0 = smem_u32(s_h + (m0 + (lane & 15)) * 264 + ((lane >> 4) * 8));
    uint32_t aptr1 = aptr0 + 16 * 264 * 2;
    #pragma unroll 1
    for (int c = 0; c < 4; c++) {
        #pragma unroll
        for (int ks = 0; ks < 4; ks++) {
            int kt = c * 4 + ks;
            uint32_t koff = (uint32_t)(kt * 16) * 2u;
            uint32_t a00, a01, a02, a03, a10, a11, a12, a13;
            LDSM_X4(a00, a01, a02, a03, aptr0 + koff);
            LDSM_X4(a10, a11, a12, a13, aptr1 + koff);
            #pragma unroll
            for (int nt = 0; nt < 4; nt++) {
                uint2 bv = __ldg(reinterpret_cast<const uint2*>(
                                     Wp + ((nb0 + nt) * KB16 + kb0 + kt) * 128) + lane);
                MMA_F16(d[nt],     a00, a01, a02, a03, bv.x, bv.y);
                MMA_F16(d[4 + nt], a10, a11, a12, a13, bv.x, bv.y);
            }
        }
    }
    __syncthreads();
}

// stage 64 rows x 256 cols from src (row stride 256) into s_h as fp16.
__device__ __forceinline__ void stage_rows(const float* __restrict__ src,
                                           __half* s_h, int n0, int tid)
{
    int f4 = (tid & 63) * 4;
    int rb = tid >> 6;
    #pragma unroll
    for (int j = 0; j < 8; j++) {
        int row = j * 8 + rb;
        int node = n0 + row;
        if (node >= NNODE) node = NNODE - 1;
        float4 v = *reinterpret_cast<const float4*>(&src[node * HDIM + f4]);
        *reinterpret_cast<half2*>(s_h + row * 264 + f4)     = __floats2half2_rn(v.x, v.y);
        *reinterpret_cast<half2*>(s_h + row * 264 + f4 + 2) = __floats2half2_rn(v.z, v.w);
    }
}

// ---------------------------------------------------------------------------
// Precompute kernel: P = h @ W1a, Q = h @ W1b. Block = 64 nodes.
// ---------------------------------------------------------------------------
extern __shared__ float smm[];

__global__ __launch_bounds__(ETHR, 2)
void precomp_mma(const float* __restrict__ h)
{
    __half* s_h = reinterpret_cast<__half*>(smm + O_H);

    const int tid  = threadIdx.x;
    const int lane = tid & 31;
    const int wid  = tid >> 5;
    const int g    = lane >> 2;
    const int tig  = lane & 3;
    const int m0   = (wid >> 3) * 32;
    const int nb0  = (wid & 7) * 4;
    const int n0b  = nb0 * 8;
    const int n0   = blockIdx.x * ET;

    stage_rows(h, s_h, n0, tid);
    __syncthreads();

    float d[8][4];
    #pragma unroll
    for (int s = 0; s < 2; s++) {
        #pragma unroll
        for (int i = 0; i < 8; i++)
            d[i][0] = d[i][1] = d[i][2] = d[i][3] = 0.0f;
        run_gemm(s ? g_W1bt : g_W1at, 16, 0, s_h, d, m0, nb0, g, tig, lane);
        float* out = s ? g_Q : g_P;
        #pragma unroll
        for (int mt = 0; mt < 2; mt++) {
            int r0 = n0 + m0 + 16 * mt + g, r1 = r0 + 8;
            #pragma unroll
            for (int nt = 0; nt < 4; nt++) {
                int f0 = n0b + nt * 8 + 2 * tig;
                int i = mt * 4 + nt;
                if (r0 < NNODE)
                    *reinterpret_cast<float2*>(&out[r0 * HDIM + f0]) =
                        make_float2(d[i][0], d[i][1]);
                if (r1 < NNODE)
                    *reinterpret_cast<float2*>(&out[r1 * HDIM + f0]) =
                        make_float2(d[i][2], d[i][3]);
            }
        }
    }
}

// ---------------------------------------------------------------------------
// Edge kernel: one block = 64 edges, fp16 MMA GEMMs.
// ---------------------------------------------------------------------------
__global__ __launch_bounds__(ETHR, 2)
void edge_mma_kernel(const float* __restrict__ x,
                     const void* __restrict__ ei_raw,
                     const float* __restrict__ W1, const float* __restrict__ b1,
                     const float* __restrict__ b2, const float* __restrict__ cb1,
                     const float* __restrict__ C2)
{
    float*  s_f   = smm + O_F;
    int*    s_row = (int*)(smm + O_ROW);
    int*    s_col = (int*)(smm + O_COL);
    float*  s_dist = smm + O_DIST;
    float*  s_diff = smm + O_DIFF;
    float*  s_red  = smm + O_RED;
    __half* s_h    = reinterpret_cast<__half*>(smm + O_H);

    const int tid  = threadIdx.x;
    const int lane = tid & 31;
    const int wid  = tid >> 5;
    const int g    = lane >> 2;
    const int tig  = lane & 3;
    const int m0   = (wid >> 3) * 32;
    const int nb0  = (wid & 7) * 4;
    const int n0b  = nb0 * 8;
    const int ng   = wid & 7;
    const int e0   = blockIdx.x * ET;

    if (tid < ET) {
        int e = e0 + tid;
        int r, c;
        if (g_is64) {
            const long long* p = (const long long*)ei_raw;
            r = (int)p[e];
            c = (int)p[NEDGE + e];
        } else {
            const int* p = (const int*)ei_raw;
            r = p[e];
            c = p[NEDGE + e];
        }
        s_row[tid] = r;
        s_col[tid] = c;
        float dx = x[r * 3 + 0] - x[c * 3 + 0];
        float dy = x[r * 3 + 1] - x[c * 3 + 1];
        float dz = x[r * 3 + 2] - x[c * 3 + 2];
        s_diff[tid * 3 + 0] = dx;
        s_diff[tid * 3 + 1] = dy;
        s_diff[tid * 3 + 2] = dz;
        s_dist[tid] = dx * dx + dy * dy + dz * dz;
    }
    __syncthreads();

    // ---- phase B: m = silu(P[row]+Q[col]+dist*w1d+b1) -> s_h (fp16) ----
    {
        int f2 = (tid & 127) * 2;
        int eh = tid >> 7;                 // 0..3, 16 edges each
        float2 w1d = *reinterpret_cast<const float2*>(&W1[512 * HDIM + f2]);
        float2 b1f = *reinterpret_cast<const float2*>(&b1[f2]);
        #pragma unroll 4
        for (int j = 0; j < 16; j++) {
            int e = eh * 16 + j;
            int r = s_row[e], c = s_col[e];
            float2 P2 = *reinterpret_cast<const float2*>(&g_P[r * HDIM + f2]);
            float2 Q2 = *reinterpret_cast<const float2*>(&g_Q[c * HDIM + f2]);
            float de = s_dist[e];
            float v0 = fmaf(de, w1d.x, P2.x + Q2.x + b1f.x);
            float v1 = fmaf(de, w1d.y, P2.y + Q2.y + b1f.y);
            *reinterpret_cast<half2*>(s_h + e * 264 + f2) =
                __floats2half2_rn(silu_f(v0), silu_f(v1));
        }
    }
    __syncthreads();

    float d[8][4];

    // ---- GEMM1: D = m @ W2 ----
    #pragma unroll
    for (int i = 0; i < 8; i++)
        d[i][0] = d[i][1] = d[i][2] = d[i][3] = 0.0f;
    run_gemm(g_W2t, 16, 0, s_h, d, m0, nb0, g, tig, lane);

    // ---- readback1: m_ij = silu(D + b2) -> s_f (exact fp32) ----
    #pragma unroll
    for (int mt = 0; mt < 2; mt++) {
        int er = m0 + 16 * mt + g;
        #pragma unroll
        for (int nt = 0; nt < 4; nt++) {
            int f0 = n0b + nt * 8 + 2 * tig;
            int i = mt * 4 + nt;
            float2 v01 = make_float2(silu_f(d[i][0] + b2[f0]),
                                     silu_f(d[i][1] + b2[f0 + 1]));
            float2 v23 = make_float2(silu_f(d[i][2] + b2[f0]),
                                     silu_f(d[i][3] + b2[f0 + 1]));
            *reinterpret_cast<float2*>(&s_f[er * 260 + f0])       = v01;
            *reinterpret_cast<float2*>(&s_f[(er + 8) * 260 + f0]) = v23;
        }
    }
    __syncthreads();

    // ---- scatter exact m_ij; write fp16 copy to s_h for GEMM2 ----
    {
        int f4 = (tid & 63) * 4;
        int eh = tid >> 6;
        #pragma unroll
        for (int j = 0; j < 8; j++) {
            int e = eh * 8 + j;
            float4 v = *reinterpret_cast<float4*>(&s_f[e * 260 + f4]);
            atomicAdd(reinterpret_cast<float4*>(&g_msg[s_col[e] * HDIM + f4]), v);
            *reinterpret_cast<half2*>(s_h + e * 264 + f4)     = __floats2half2_rn(v.x, v.y);
            *reinterpret_cast<half2*>(s_h + e * 264 + f4 + 2) = __floats2half2_rn(v.z, v.w);
        }
    }
    __syncthreads();

    // ---- GEMM2: D = m_ij @ C1 ----
    #pragma unroll
    for (int i = 0; i < 8; i++)
        d[i][0] = d[i][1] = d[i][2] = d[i][3] = 0.0f;
    run_gemm(g_C1t, 16, 0, s_h, d, m0, nb0, g, tig, lane);

    // ---- readback2: coord_weight = sum_f silu(D + cb1) * C2 ----
    {
        float cw[2][2] = {{0.0f, 0.0f}, {0.0f, 0.0f}};
        #pragma unroll
        for (int mt = 0; mt < 2; mt++) {
            #pragma unroll
            for (int nt = 0; nt < 4; nt++) {
                int f0 = n0b + nt * 8 + 2 * tig;
                int i = mt * 4 + nt;
                float c20 = C2[f0], c21 = C2[f0 + 1];
                float bb0 = cb1[f0], bb1 = cb1[f0 + 1];
                cw[mt][0] += silu_f(d[i][0] + bb0) * c20 + silu_f(d[i][1] + bb1) * c21;
                cw[mt][1] += silu_f(d[i][2] + bb0) * c20 + silu_f(d[i][3] + bb1) * c21;
            }
        }
        #pragma unroll
        for (int mt = 0; mt < 2; mt++) {
            #pragma unroll
            for (int hh = 0; hh < 2; hh++) {
                float v = cw[mt][hh];
                v += __shfl_xor_sync(0xFFFFFFFFu, v, 1);
                v += __shfl_xor_sync(0xFFFFFFFFu, v, 2);
                if (tig == 0)
                    s_red[(m0 + 16 * mt + g + 8 * hh) * 8 + ng] = v;
            }
        }
    }
    __syncthreads();
    if (tid < ET) {
        float w = 0.0f;
        #pragma unroll
        for (int j = 0; j < 8; j++) w += s_red[tid * 8 + j];
        int c = s_col[tid];
        atomicAdd(&g_coord[c * 3 + 0], w * s_diff[tid * 3 + 0]);
        atomicAdd(&g_coord[c * 3 + 1], w * s_diff[tid * 3 + 1]);
        atomicAdd(&g_coord[c * 3 + 2], w * s_diff[tid * 3 + 2]);
    }
}

// ---------------------------------------------------------------------------
// Node kernel: block = 64 nodes. GEMM1 (K=512, two halves), SiLU, GEMM2,
// residual + LayerNorm epilogue.
// ---------------------------------------------------------------------------
__global__ __launch_bounds__(ETHR, 2)
void node_mma(const float* __restrict__ h,
              const float* __restrict__ nb1, const float* __restrict__ nb2,
              const float* __restrict__ lng, const float* __restrict__ lnb,
              float* __restrict__ out_h)
{
    float*  s_r1 = smm + O_R1;
    float*  s_r2 = smm + O_R2;
    float*  s_mu = smm + O_MU;
    float*  s_rs = smm + O_RS;
    __half* s_h  = reinterpret_cast<__half*>(smm + O_H);

    const int tid  = threadIdx.x;
    const int lane = tid & 31;
    const int wid  = tid >> 5;
    const int g    = lane >> 2;
    const int tig  = lane & 3;
    const int m0   = (wid >> 3) * 32;
    const int nb0  = (wid & 7) * 4;
    const int n0b  = nb0 * 8;
    const int ng   = wid & 7;
    const int n0   = blockIdx.x * ET;

    float d[8][4];

    #pragma unroll
    for (int mt = 0; mt < 2; mt++)
        #pragma unroll
        for (int nt = 0; nt < 4; nt++) {
            int f0 = n0b + nt * 8 + 2 * tig;
            int i = mt * 4 + nt;
            d[i][0] = nb1[f0]; d[i][1] = nb1[f0 + 1];
            d[i][2] = d[i][0]; d[i][3] = d[i][1];
        }
    stage_rows(h, s_h, n0, tid);
    __syncthreads();
    run_gemm(g_NW1t, 32, 0, s_h, d, m0, nb0, g, tig, lane);

    stage_rows(g_msg, s_h, n0, tid);
    __syncthreads();
    run_gemm(g_NW1t, 32, 16, s_h, d, m0, nb0, g, tig, lane);

    // u = silu(.) -> s_h (fp16) for GEMM2
    #pragma unroll
    for (int mt = 0; mt < 2; mt++) {
        int r = m0 + 16 * mt + g;
        #pragma unroll
        for (int nt = 0; nt < 4; nt++) {
            int f0 = n0b + nt * 8 + 2 * tig;
            int i = mt * 4 + nt;
            *reinterpret_cast<half2*>(s_h + r * 264 + f0) =
                __floats2half2_rn(silu_f(d[i][0]), silu_f(d[i][1]));
            *reinterpret_cast<half2*>(s_h + (r + 8) * 264 + f0) =
                __floats2half2_rn(silu_f(d[i][2]), silu_f(d[i][3]));
        }
    }
    __syncthreads();

    #pragma unroll
    for (int mt = 0; mt < 2; mt++)
        #pragma unroll
        for (int nt = 0; nt < 4; nt++) {
            int f0 = n0b + nt * 8 + 2 * tig;
            int i = mt * 4 + nt;
            d[i][0] = nb2[f0]; d[i][1] = nb2[f0 + 1];
            d[i][2] = d[i][0]; d[i][3] = d[i][1];
        }
    run_gemm(g_NW2t, 16, 0, s_h, d, m0, nb0, g, tig, lane);

    float s1[2][2] = {{0, 0}, {0, 0}}, s2[2][2] = {{0, 0}, {0, 0}};
    #pragma unroll
    for (int mt = 0; mt < 2; mt++) {
        int gr0 = n0 + m0 + 16 * mt + g, gr1 = gr0 + 8;
        #pragma unroll
        for (int nt = 0; nt < 4; nt++) {
            int f0 = n0b + nt * 8 + 2 * tig;
            int i = mt * 4 + nt;
            float2 h0 = (gr0 < NNODE)
                ? *reinterpret_cast<const float2*>(&h[gr0 * HDIM + f0])
                : make_float2(0.0f, 0.0f);
            float2 h1 = (gr1 < NNODE)
                ? *reinterpret_cast<const float2*>(&h[gr1 * HDIM + f0])
                : make_float2(0.0f, 0.0f);
            d[i][0] += h0.x; d[i][1] += h0.y;
            d[i][2] += h1.x; d[i][3] += h1.y;
            s1[mt][0] += d[i][0] + d[i][1];
            s2[mt][0] += d[i][0] * d[i][0] + d[i][1] * d[i][1];
            s1[mt][1] += d[i][2] + d[i][3];
            s2[mt][1] += d[i][2] * d[i][2] + d[i][3] * d[i][3];
        }
    }
    #pragma unroll
    for (int mt = 0; mt < 2; mt++)
        #pragma unroll
        for (int hh = 0; hh < 2; hh++) {
            float v1 = s1[mt][hh], v2 = s2[mt][hh];
            v1 += __shfl_xor_sync(0xFFFFFFFFu, v1, 1);
            v1 += __shfl_xor_sync(0xFFFFFFFFu, v1, 2);
            v2 += __shfl_xor_sync(0xFFFFFFFFu, v2, 1);
            v2 += __shfl_xor_sync(0xFFFFFFFFu, v2, 2);
            if (tig == 0) {
                int row = m0 + 16 * mt + g + 8 * hh;
                s_r1[row * 8 + ng] = v1;
                s_r2[row * 8 + ng] = v2;
            }
        }
    __syncthreads();
    if (tid < ET) {
        float S1 = 0.0f, S2 = 0.0f;
        #pragma unroll
        for (int j = 0; j < 8; j++) { S1 += s_r1[tid * 8 + j]; S2 += s_r2[tid * 8 + j]; }
        float mu  = S1 * (1.0f / HDIM);
        float var = S2 * (1.0f / HDIM) - mu * mu;
        s_mu[tid] = mu;
        s_rs[tid] = rsqrtf(var + LN_EPS);
    }
    __syncthreads();
    #pragma unroll
    for (int mt = 0; mt < 2; mt++) {
        int row0 = m0 + 16 * mt + g;
        int gr0 = n0 + row0, gr1 = gr0 + 8;
        float mu0 = s_mu[row0],     rs0 = s_rs[row0];
        float mu1 = s_mu[row0 + 8], rs1 = s_rs[row0 + 8];
        #pragma unroll
        for (int nt = 0; nt < 4; nt++) {
            int f0 = n0b + nt * 8 + 2 * tig;
            int i = mt * 4 + nt;
            float g0 = lng[f0], g1 = lng[f0 + 1];
            float b0 = lnb[f0], b1v = lnb[f0 + 1];
            if (gr0 < NNODE)
                *reinterpret_cast<float2*>(&out_h[gr0 * HDIM + f0]) =
                    make_float2((d[i][0] - mu0) * rs0 * g0 + b0,
                                (d[i][1] - mu0) * rs0 * g1 + b1v);
            if (gr1 < NNODE)
                *reinterpret_cast<float2*>(&out_h[gr1 * HDIM + f0]) =
                    make_float2((d[i][2] - mu1) * rs1 * g0 + b0,
                                (d[i][3] - mu1) * rs1 * g1 + b1v);
        }
    }
}

// ---------------------------------------------------------------------------
__global__ void xnew_kernel(const float* __restrict__ x, float* __restrict__ out_x) {
    int i = blockIdx.x * blockDim.x + threadIdx.x;
    if (i < NNODE * 3) out_x[i] = x[i] + g_coord[i];
}

// ---------------------------------------------------------------------------
extern "C" void kernel_launch(void* const* d_in, const int* in_sizes, int n_in,
                              void* d_out, int out_size)
{
    const float* h    = (const float*)d_in[0];
    const float* x    = (const float*)d_in[1];
    const void*  ei   = d_in[2];
    const float* e_w1 = (const float*)d_in[3];
    const float* e_b1 = (const float*)d_in[4];
    const float* e_w2 = (const float*)d_in[5];
    const float* e_b2 = (const float*)d_in[6];
    const float* c_w1 = (const float*)d_in[7];
    const float* c_b1 = (const float*)d_in[8];
    const float* c_w2 = (const float*)d_in[9];
    const float* n_w1 = (const float*)d_in[10];
    const float* n_b1 = (const float*)d_in[11];
    const float* n_w2 = (const float*)d_in[12];
    const float* n_b2 = (const float*)d_in[13];
    const float* ln_g = (const float*)d_in[14];
    const float* ln_b = (const float*)d_in[15];
    float* out = (float*)d_out;

    cudaFuncSetAttribute(precomp_mma,     cudaFuncAttributeMaxDynamicSharedMemorySize, MMA_SMEM);
    cudaFuncSetAttribute(edge_mma_kernel, cudaFuncAttributeMaxDynamicSharedMemorySize, MMA_SMEM);
    cudaFuncSetAttribute(node_mma,        cudaFuncAttributeMaxDynamicSharedMemorySize, MMA_SMEM);

    const int nblk = (NNODE + ET - 1) / ET;

    detect_kernel<<<1, 32>>>((const unsigned*)ei);
    zero_kernel<<<512, 256>>>();
    transpose_kernel<<<dim3(8, 8, 7), dim3(32, 8)>>>(e_w2, c_w1, e_w1, n_w1, n_w2);
    precomp_mma<<<nblk, ETHR, MMA_SMEM>>>(h);
    edge_mma_kernel<<<NEDGE / ET, ETHR, MMA_SMEM>>>(x, ei, e_w1, e_b1,
                                                    e_b2, c_b1, c_w2);
    node_mma<<<nblk, ETHR, MMA_SMEM>>>(h, n_b1, n_b2, ln_g, ln_b, out);
    xnew_kernel<<<(NNODE * 3 + 255) / 256, 256>>>(x, out + NNODE * HDIM);
}

// round 15
// speedup vs baseline: 1.1884x; 1.1884x over previous
#include <cuda_runtime.h>
#include <cuda_fp16.h>
#include <cstdint>

// ---------------------------------------------------------------------------
// EGNN layer: N=20000 nodes, E=320000 edges, H=256.
// Round 15: exact R12 GEMM loop (fp16 m16n8k16, ET=64, 2Mx8N, 2 CTA/SM),
// but SMEM shrunk 105KB -> ~37KB/CTA so B-operand __ldg traffic caches in L1
// (was: 210KB carveout left ~18KB L1 -> every B load was an L2 hit).
// Edge m_ij scatter now goes directly from registers (exact fp32 preserved).
// ---------------------------------------------------------------------------

#define HDIM    256
#define NNODE   20000
#define NEDGE   320000
#define LN_EPS  1e-5f

#define ET      64           // rows per MMA block
#define ETHR    512          // threads (16 warps: 2M x 8N)

// edge smem (float offsets): misc then fp16 buffer
#define E_ROW   0            // 64 int
#define E_COL   64
#define E_DIST  128
#define E_DIFF  192          // 192 f
#define E_RED   384          // 512 f
#define E_H     896          // halves start here (64 x 264)
#define EDGE_SMEM (896 * 4 + 64 * 264 * 2)    // 37376 B

// node smem
#define N_R1    0            // 512 f
#define N_R2    512          // 512 f
#define N_MU    1024         // 64 f
#define N_RS    1088         // 64 f
#define N_H     1152
#define NODE_SMEM (1152 * 4 + 64 * 264 * 2)   // 38400 B

#define PREC_SMEM (64 * 264 * 2)              // 33792 B

__device__ float g_msg[NNODE * HDIM];
__device__ float g_P[NNODE * HDIM];
__device__ float g_Q[NNODE * HDIM];
__device__ float g_coord[NNODE * 3];
// fragment-packed fp16 weights: tile(nb,kt) = 128 halves, per-lane uint2
__device__ __half g_W2t[HDIM * HDIM];
__device__ __half g_C1t[HDIM * HDIM];
__device__ __half g_W1at[HDIM * HDIM];
__device__ __half g_W1bt[HDIM * HDIM];
__device__ __half g_NW1t[HDIM * 2 * HDIM];   // K = 512 (KB16 = 32)
__device__ __half g_NW2t[HDIM * HDIM];
__device__ int   g_is64;

__device__ __forceinline__ float silu_f(float v) {
    return v / (1.0f + __expf(-v));
}

#define MMA_F16(D, A0, A1, A2, A3, B0, B1)                                    \
    asm volatile(                                                             \
        "mma.sync.aligned.m16n8k16.row.col.f32.f16.f16.f32 "                  \
        "{%0,%1,%2,%3}, {%4,%5,%6,%7}, {%8,%9}, {%0,%1,%2,%3};"               \
        : "+f"((D)[0]), "+f"((D)[1]), "+f"((D)[2]), "+f"((D)[3])              \
        : "r"(A0), "r"(A1), "r"(A2), "r"(A3), "r"(B0), "r"(B1))

// ---------------------------------------------------------------------------
__global__ void detect_kernel(const unsigned* __restrict__ w) {
    unsigned acc = 0;
    for (int i = threadIdx.x; i < 1024; i += 32) acc |= w[2 * i + 1];
    #pragma unroll
    for (int o = 16; o; o >>= 1) acc |= __shfl_xor_sync(0xFFFFFFFFu, acc, o);
    if (threadIdx.x == 0) g_is64 = (acc == 0) ? 1 : 0;
}

__global__ void zero_kernel() {
    int i = blockIdx.x * blockDim.x + threadIdx.x;
    int stride = gridDim.x * blockDim.x;
    for (int idx = i; idx < NNODE * HDIM; idx += stride) g_msg[idx] = 0.0f;
    for (int idx = i; idx < NNODE * 3;    idx += stride) g_coord[idx] = 0.0f;
}

// transpose + fp16-round + fragment-pack all weight matrices (R12 layout).
__global__ void transpose_kernel(const float* __restrict__ W2,
                                 const float* __restrict__ C1,
                                 const float* __restrict__ EW1,
                                 const float* __restrict__ NW1,
                                 const float* __restrict__ NW2) {
    __shared__ float t[32][33];
    const float* src; __half* dst; int kdim = HDIM; int doff = 0;
    switch (blockIdx.z) {
        case 0: src = W2;                dst = g_W2t;  break;
        case 1: src = C1;                dst = g_C1t;  break;
        case 2: src = EW1;               dst = g_W1at; break;
        case 3: src = EW1 + HDIM * HDIM; dst = g_W1bt; break;
        case 4: src = NW1;               dst = g_NW1t; kdim = 2 * HDIM; break;
        default: src = NW1 + HDIM * HDIM; dst = g_NW1t; kdim = 2 * HDIM; doff = HDIM; break;
        case 6: src = NW2;               dst = g_NW2t; break;
    }
    int bx = blockIdx.x * 32, by = blockIdx.y * 32;
    int tx = threadIdx.x, ty = threadIdx.y;
    #pragma unroll
    for (int i = 0; i < 32; i += 8)
        t[ty + i][tx] = src[(by + ty + i) * HDIM + bx + tx];
    __syncthreads();
    int KB16 = kdim >> 4;
    #pragma unroll
    for (int i = 0; i < 32; i += 8) {
        int n = bx + ty + i;
        int k = doff + by + tx;
        int off = ((n >> 3) * KB16 + (k >> 4)) * 128
                + ((n & 7) * 4 + ((k & 7) >> 1)) * 4
                + ((k >> 3) & 1) * 2 + (k & 1);
        dst[off] = __float2half_rn(t[tx][ty + i]);
    }
}

// ---------------------------------------------------------------------------
// fp16 warp-MMA GEMM (R12 inner loop, unchanged): warp tile 32r x 32c
// (2 mt x 4 nt). Per k16-step: 8 LDS.32 (A) + 4 LDG.64 (B) + 8 MMA.
// ---------------------------------------------------------------------------
__device__ __forceinline__ void run_gemm(const __half* __restrict__ Wp,
                                         int KB16, int kb0,
                                         const __half* s_h, float d[8][4],
                                         int m0, int nb0,
                                         int g, int tig, int lane)
{
    const __half* r0 = s_h + (m0 + g) * 264 + 2 * tig;
    const __half* r1 = r0 + 8 * 264;
    const __half* r2 = r0 + 16 * 264;
    const __half* r3 = r0 + 24 * 264;
    #pragma unroll 1
    for (int c = 0; c < 4; c++) {
        #pragma unroll
        for (int ks = 0; ks < 4; ks++) {
            int kt = c * 4 + ks;
            int kh = kt * 16;
            uint32_t a00 = *reinterpret_cast<const uint32_t*>(r0 + kh);
            uint32_t a01 = *reinterpret_cast<const uint32_t*>(r1 + kh);
            uint32_t a02 = *reinterpret_cast<const uint32_t*>(r0 + kh + 8);
            uint32_t a03 = *reinterpret_cast<const uint32_t*>(r1 + kh + 8);
            uint32_t a10 = *reinterpret_cast<const uint32_t*>(r2 + kh);
            uint32_t a11 = *reinterpret_cast<const uint32_t*>(r3 + kh);
            uint32_t a12 = *reinterpret_cast<const uint32_t*>(r2 + kh + 8);
            uint32_t a13 = *reinterpret_cast<const uint32_t*>(r3 + kh + 8);
            #pragma unroll
            for (int nt = 0; nt < 4; nt++) {
                uint2 bv = __ldg(reinterpret_cast<const uint2*>(
                                     Wp + ((nb0 + nt) * KB16 + kb0 + kt) * 128) + lane);
                MMA_F16(d[nt],     a00, a01, a02, a03, bv.x, bv.y);
                MMA_F16(d[4 + nt], a10, a11, a12, a13, bv.x, bv.y);
            }
        }
    }
    __syncthreads();
}

// stage 64 rows x 256 cols from src (row stride 256) into s_h as fp16.
__device__ __forceinline__ void stage_rows(const float* __restrict__ src,
                                           __half* s_h, int n0, int tid)
{
    int f4 = (tid & 63) * 4;
    int rb = tid >> 6;
    #pragma unroll
    for (int j = 0; j < 8; j++) {
        int row = j * 8 + rb;
        int node = n0 + row;
        if (node >= NNODE) node = NNODE - 1;
        float4 v = *reinterpret_cast<const float4*>(&src[node * HDIM + f4]);
        *reinterpret_cast<half2*>(s_h + row * 264 + f4)     = __floats2half2_rn(v.x, v.y);
        *reinterpret_cast<half2*>(s_h + row * 264 + f4 + 2) = __floats2half2_rn(v.z, v.w);
    }
}

// ---------------------------------------------------------------------------
// Precompute kernel: P = h @ W1a, Q = h @ W1b. Block = 64 nodes.
// ---------------------------------------------------------------------------
extern __shared__ float smm[];

__global__ __launch_bounds__(ETHR, 2)
void precomp_mma(const float* __restrict__ h)
{
    __half* s_h = reinterpret_cast<__half*>(smm);

    const int tid  = threadIdx.x;
    const int lane = tid & 31;
    const int wid  = tid >> 5;
    const int g    = lane >> 2;
    const int tig  = lane & 3;
    const int m0   = (wid >> 3) * 32;
    const int nb0  = (wid & 7) * 4;
    const int n0b  = nb0 * 8;
    const int n0   = blockIdx.x * ET;

    stage_rows(h, s_h, n0, tid);
    __syncthreads();

    float d[8][4];
    #pragma unroll
    for (int s = 0; s < 2; s++) {
        #pragma unroll
        for (int i = 0; i < 8; i++)
            d[i][0] = d[i][1] = d[i][2] = d[i][3] = 0.0f;
        run_gemm(s ? g_W1bt : g_W1at, 16, 0, s_h, d, m0, nb0, g, tig, lane);
        float* out = s ? g_Q : g_P;
        #pragma unroll
        for (int mt = 0; mt < 2; mt++) {
            int r0 = n0 + m0 + 16 * mt + g, r1 = r0 + 8;
            #pragma unroll
            for (int nt = 0; nt < 4; nt++) {
                int f0 = n0b + nt * 8 + 2 * tig;
                int i = mt * 4 + nt;
                if (r0 < NNODE)
                    *reinterpret_cast<float2*>(&out[r0 * HDIM + f0]) =
                        make_float2(d[i][0], d[i][1]);
                if (r1 < NNODE)
                    *reinterpret_cast<float2*>(&out[r1 * HDIM + f0]) =
                        make_float2(d[i][2], d[i][3]);
            }
        }
    }
}

// ---------------------------------------------------------------------------
// Edge kernel: one block = 64 edges, fp16 MMA GEMMs, register-direct scatter.
// ---------------------------------------------------------------------------
__global__ __launch_bounds__(ETHR, 2)
void edge_mma_kernel(const float* __restrict__ x,
                     const void* __restrict__ ei_raw,
                     const float* __restrict__ W1, const float* __restrict__ b1,
                     const float* __restrict__ b2, const float* __restrict__ cb1,
                     const float* __restrict__ C2)
{
    int*    s_row  = (int*)(smm + E_ROW);
    int*    s_col  = (int*)(smm + E_COL);
    float*  s_dist = smm + E_DIST;
    float*  s_diff = smm + E_DIFF;
    float*  s_red  = smm + E_RED;
    __half* s_h    = reinterpret_cast<__half*>(smm + E_H);

    const int tid  = threadIdx.x;
    const int lane = tid & 31;
    const int wid  = tid >> 5;
    const int g    = lane >> 2;
    const int tig  = lane & 3;
    const int m0   = (wid >> 3) * 32;
    const int nb0  = (wid & 7) * 4;
    const int n0b  = nb0 * 8;
    const int ng   = wid & 7;
    const int e0   = blockIdx.x * ET;

    if (tid < ET) {
        int e = e0 + tid;
        int r, c;
        if (g_is64) {
            const long long* p = (const long long*)ei_raw;
            r = (int)p[e];
            c = (int)p[NEDGE + e];
        } else {
            const int* p = (const int*)ei_raw;
            r = p[e];
            c = p[NEDGE + e];
        }
        s_row[tid] = r;
        s_col[tid] = c;
        float dx = x[r * 3 + 0] - x[c * 3 + 0];
        float dy = x[r * 3 + 1] - x[c * 3 + 1];
        float dz = x[r * 3 + 2] - x[c * 3 + 2];
        s_diff[tid * 3 + 0] = dx;
        s_diff[tid * 3 + 1] = dy;
        s_diff[tid * 3 + 2] = dz;
        s_dist[tid] = dx * dx + dy * dy + dz * dz;
    }
    __syncthreads();

    // ---- phase B: m = silu(P[row]+Q[col]+dist*w1d+b1) -> s_h (fp16) ----
    {
        int f2 = (tid & 127) * 2;
        int eh = tid >> 7;                 // 0..3, 16 edges each
        float2 w1d = *reinterpret_cast<const float2*>(&W1[512 * HDIM + f2]);
        float2 b1f = *reinterpret_cast<const float2*>(&b1[f2]);
        #pragma unroll 4
        for (int j = 0; j < 16; j++) {
            int e = eh * 16 + j;
            int r = s_row[e], c = s_col[e];
            float2 P2 = *reinterpret_cast<const float2*>(&g_P[r * HDIM + f2]);
            float2 Q2 = *reinterpret_cast<const float2*>(&g_Q[c * HDIM + f2]);
            float de = s_dist[e];
            float v0 = fmaf(de, w1d.x, P2.x + Q2.x + b1f.x);
            float v1 = fmaf(de, w1d.y, P2.y + Q2.y + b1f.y);
            *reinterpret_cast<half2*>(s_h + e * 264 + f2) =
                __floats2half2_rn(silu_f(v0), silu_f(v1));
        }
    }
    __syncthreads();

    float d[8][4];

    // ---- GEMM1: D = m @ W2 ----
    #pragma unroll
    for (int i = 0; i < 8; i++)
        d[i][0] = d[i][1] = d[i][2] = d[i][3] = 0.0f;
    run_gemm(g_W2t, 16, 0, s_h, d, m0, nb0, g, tig, lane);

    // ---- readback1: m_ij = silu(D + b2); direct exact-fp32 scatter;
    //      fp16 copy into s_h (m dead after GEMM1's closing barrier) ----
    #pragma unroll
    for (int mt = 0; mt < 2; mt++) {
        int er = m0 + 16 * mt + g;
        int c0 = s_col[er];
        int c1 = s_col[er + 8];
        #pragma unroll
        for (int nt = 0; nt < 4; nt++) {
            int f0 = n0b + nt * 8 + 2 * tig;
            int i = mt * 4 + nt;
            float m00 = silu_f(d[i][0] + b2[f0]);
            float m01 = silu_f(d[i][1] + b2[f0 + 1]);
            float m10 = silu_f(d[i][2] + b2[f0]);
            float m11 = silu_f(d[i][3] + b2[f0 + 1]);
            atomicAdd(reinterpret_cast<float2*>(&g_msg[c0 * HDIM + f0]),
                      make_float2(m00, m01));
            atomicAdd(reinterpret_cast<float2*>(&g_msg[c1 * HDIM + f0]),
                      make_float2(m10, m11));
            *reinterpret_cast<half2*>(s_h + er * 264 + f0)       = __floats2half2_rn(m00, m01);
            *reinterpret_cast<half2*>(s_h + (er + 8) * 264 + f0) = __floats2half2_rn(m10, m11);
        }
    }
    __syncthreads();

    // ---- GEMM2: D = m_ij @ C1 ----
    #pragma unroll
    for (int i = 0; i < 8; i++)
        d[i][0] = d[i][1] = d[i][2] = d[i][3] = 0.0f;
    run_gemm(g_C1t, 16, 0, s_h, d, m0, nb0, g, tig, lane);

    // ---- readback2: coord_weight = sum_f silu(D + cb1) * C2 ----
    {
        float cw[2][2] = {{0.0f, 0.0f}, {0.0f, 0.0f}};
        #pragma unroll
        for (int mt = 0; mt < 2; mt++) {
            #pragma unroll
            for (int nt = 0; nt < 4; nt++) {
                int f0 = n0b + nt * 8 + 2 * tig;
                int i = mt * 4 + nt;
                float c20 = C2[f0], c21 = C2[f0 + 1];
                float bb0 = cb1[f0], bb1 = cb1[f0 + 1];
                cw[mt][0] += silu_f(d[i][0] + bb0) * c20 + silu_f(d[i][1] + bb1) * c21;
                cw[mt][1] += silu_f(d[i][2] + bb0) * c20 + silu_f(d[i][3] + bb1) * c21;
            }
        }
        #pragma unroll
        for (int mt = 0; mt < 2; mt++) {
            #pragma unroll
            for (int hh = 0; hh < 2; hh++) {
                float v = cw[mt][hh];
                v += __shfl_xor_sync(0xFFFFFFFFu, v, 1);
                v += __shfl_xor_sync(0xFFFFFFFFu, v, 2);
                if (tig == 0)
                    s_red[(m0 + 16 * mt + g + 8 * hh) * 8 + ng] = v;
            }
        }
    }
    __syncthreads();
    if (tid < ET) {
        float w = 0.0f;
        #pragma unroll
        for (int j = 0; j < 8; j++) w += s_red[tid * 8 + j];
        int c = s_col[tid];
        atomicAdd(&g_coord[c * 3 + 0], w * s_diff[tid * 3 + 0]);
        atomicAdd(&g_coord[c * 3 + 1], w * s_diff[tid * 3 + 1]);
        atomicAdd(&g_coord[c * 3 + 2], w * s_diff[tid * 3 + 2]);
    }
}

// ---------------------------------------------------------------------------
// Node kernel: block = 64 nodes. GEMM1 (K=512, two halves), SiLU, GEMM2,
// residual + LayerNorm epilogue.
// ---------------------------------------------------------------------------
__global__ __launch_bounds__(ETHR, 2)
void node_mma(const float* __restrict__ h,
              const float* __restrict__ nb1, const float* __restrict__ nb2,
              const float* __restrict__ lng, const float* __restrict__ lnb,
              float* __restrict__ out_h)
{
    float*  s_r1 = smm + N_R1;
    float*  s_r2 = smm + N_R2;
    float*  s_mu = smm + N_MU;
    float*  s_rs = smm + N_RS;
    __half* s_h  = reinterpret_cast<__half*>(smm + N_H);

    const int tid  = threadIdx.x;
    const int lane = tid & 31;
    const int wid  = tid >> 5;
    const int g    = lane >> 2;
    const int tig  = lane & 3;
    const int m0   = (wid >> 3) * 32;
    const int nb0  = (wid & 7) * 4;
    const int n0b  = nb0 * 8;
    const int ng   = wid & 7;
    const int n0   = blockIdx.x * ET;

    float d[8][4];

    #pragma unroll
    for (int mt = 0; mt < 2; mt++)
        #pragma unroll
        for (int nt = 0; nt < 4; nt++) {
            int f0 = n0b + nt * 8 + 2 * tig;
            int i = mt * 4 + nt;
            d[i][0] = nb1[f0]; d[i][1] = nb1[f0 + 1];
            d[i][2] = d[i][0]; d[i][3] = d[i][1];
        }
    stage_rows(h, s_h, n0, tid);
    __syncthreads();
    run_gemm(g_NW1t, 32, 0, s_h, d, m0, nb0, g, tig, lane);

    stage_rows(g_msg, s_h, n0, tid);
    __syncthreads();
    run_gemm(g_NW1t, 32, 16, s_h, d, m0, nb0, g, tig, lane);

    // u = silu(.) -> s_h (fp16) for GEMM2
    #pragma unroll
    for (int mt = 0; mt < 2; mt++) {
        int r = m0 + 16 * mt + g;
        #pragma unroll
        for (int nt = 0; nt < 4; nt++) {
            int f0 = n0b + nt * 8 + 2 * tig;
            int i = mt * 4 + nt;
            *reinterpret_cast<half2*>(s_h + r * 264 + f0) =
                __floats2half2_rn(silu_f(d[i][0]), silu_f(d[i][1]));
            *reinterpret_cast<half2*>(s_h + (r + 8) * 264 + f0) =
                __floats2half2_rn(silu_f(d[i][2]), silu_f(d[i][3]));
        }
    }
    __syncthreads();

    #pragma unroll
    for (int mt = 0; mt < 2; mt++)
        #pragma unroll
        for (int nt = 0; nt < 4; nt++) {
            int f0 = n0b + nt * 8 + 2 * tig;
            int i = mt * 4 + nt;
            d[i][0] = nb2[f0]; d[i][1] = nb2[f0 + 1];
            d[i][2] = d[i][0]; d[i][3] = d[i][1];
        }
    run_gemm(g_NW2t, 16, 0, s_h, d, m0, nb0, g, tig, lane);

    float s1[2][2] = {{0, 0}, {0, 0}}, s2[2][2] = {{0, 0}, {0, 0}};
    #pragma unroll
    for (int mt = 0; mt < 2; mt++) {
        int gr0 = n0 + m0 + 16 * mt + g, gr1 = gr0 + 8;
        #pragma unroll
        for (int nt = 0; nt < 4; nt++) {
            int f0 = n0b + nt * 8 + 2 * tig;
            int i = mt * 4 + nt;
            float2 h0 = (gr0 < NNODE)
                ? *reinterpret_cast<const float2*>(&h[gr0 * HDIM + f0])
                : make_float2(0.0f, 0.0f);
            float2 h1 = (gr1 < NNODE)
                ? *reinterpret_cast<const float2*>(&h[gr1 * HDIM + f0])
                : make_float2(0.0f, 0.0f);
            d[i][0] += h0.x; d[i][1] += h0.y;
            d[i][2] += h1.x; d[i][3] += h1.y;
            s1[mt][0] += d[i][0] + d[i][1];
            s2[mt][0] += d[i][0] * d[i][0] + d[i][1] * d[i][1];
            s1[mt][1] += d[i][2] + d[i][3];
            s2[mt][1] += d[i][2] * d[i][2] + d[i][3] * d[i][3];
        }
    }
    #pragma unroll
    for (int mt = 0; mt < 2; mt++)
        #pragma unroll
        for (int hh = 0; hh < 2; hh++) {
            float v1 = s1[mt][hh], v2 = s2[mt][hh];
            v1 += __shfl_xor_sync(0xFFFFFFFFu, v1, 1);
            v1 += __shfl_xor_sync(0xFFFFFFFFu, v1, 2);
            v2 += __shfl_xor_sync(0xFFFFFFFFu, v2, 1);
            v2 += __shfl_xor_sync(0xFFFFFFFFu, v2, 2);
            if (tig == 0) {
                int row = m0 + 16 * mt + g + 8 * hh;
                s_r1[row * 8 + ng] = v1;
                s_r2[row * 8 + ng] = v2;
            }
        }
    __syncthreads();
    if (tid < ET) {
        float S1 = 0.0f, S2 = 0.0f;
        #pragma unroll
        for (int j = 0; j < 8; j++) { S1 += s_r1[tid * 8 + j]; S2 += s_r2[tid * 8 + j]; }
        float mu  = S1 * (1.0f / HDIM);
        float var = S2 * (1.0f / HDIM) - mu * mu;
        s_mu[tid] = mu;
        s_rs[tid] = rsqrtf(var + LN_EPS);
    }
    __syncthreads();
    #pragma unroll
    for (int mt = 0; mt < 2; mt++) {
        int row0 = m0 + 16 * mt + g;
        int gr0 = n0 + row0, gr1 = gr0 + 8;
        float mu0 = s_mu[row0],     rs0 = s_rs[row0];
        float mu1 = s_mu[row0 + 8], rs1 = s_rs[row0 + 8];
        #pragma unroll
        for (int nt = 0; nt < 4; nt++) {
            int f0 = n0b + nt * 8 + 2 * tig;
            int i = mt * 4 + nt;
            float g0 = lng[f0], g1 = lng[f0 + 1];
            float b0 = lnb[f0], b1v = lnb[f0 + 1];
            if (gr0 < NNODE)
                *reinterpret_cast<float2*>(&out_h[gr0 * HDIM + f0]) =
                    make_float2((d[i][0] - mu0) * rs0 * g0 + b0,
                                (d[i][1] - mu0) * rs0 * g1 + b1v);
            if (gr1 < NNODE)
                *reinterpret_cast<float2*>(&out_h[gr1 * HDIM + f0]) =
                    make_float2((d[i][2] - mu1) * rs1 * g0 + b0,
                                (d[i][3] - mu1) * rs1 * g1 + b1v);
        }
    }
}

// ---------------------------------------------------------------------------
__global__ void xnew_kernel(const float* __restrict__ x, float* __restrict__ out_x) {
    int i = blockIdx.x * blockDim.x + threadIdx.x;
    if (i < NNODE * 3) out_x[i] = x[i] + g_coord[i];
}

// ---------------------------------------------------------------------------
extern "C" void kernel_launch(void* const* d_in, const int* in_sizes, int n_in,
                              void* d_out, int out_size)
{
    const float* h    = (const float*)d_in[0];
    const float* x    = (const float*)d_in[1];
    const void*  ei   = d_in[2];
    const float* e_w1 = (const float*)d_in[3];
    const float* e_b1 = (const float*)d_in[4];
    const float* e_w2 = (const float*)d_in[5];
    const float* e_b2 = (const float*)d_in[6];
    const float* c_w1 = (const float*)d_in[7];
    const float* c_b1 = (const float*)d_in[8];
    const float* c_w2 = (const float*)d_in[9];
    const float* n_w1 = (const float*)d_in[10];
    const float* n_b1 = (const float*)d_in[11];
    const float* n_w2 = (const float*)d_in[12];
    const float* n_b2 = (const float*)d_in[13];
    const float* ln_g = (const float*)d_in[14];
    const float* ln_b = (const float*)d_in[15];
    float* out = (float*)d_out;

    cudaFuncSetAttribute(precomp_mma,     cudaFuncAttributeMaxDynamicSharedMemorySize, PREC_SMEM);
    cudaFuncSetAttribute(edge_mma_kernel, cudaFuncAttributeMaxDynamicSharedMemorySize, EDGE_SMEM);
    cudaFuncSetAttribute(node_mma,        cudaFuncAttributeMaxDynamicSharedMemorySize, NODE_SMEM);

    const int nblk = (NNODE + ET - 1) / ET;

    detect_kernel<<<1, 32>>>((const unsigned*)ei);
    zero_kernel<<<512, 256>>>();
    transpose_kernel<<<dim3(8, 8, 7), dim3(32, 8)>>>(e_w2, c_w1, e_w1, n_w1, n_w2);
    precomp_mma<<<nblk, ETHR, PREC_SMEM>>>(h);
    edge_mma_kernel<<<NEDGE / ET, ETHR, EDGE_SMEM>>>(x, ei, e_w1, e_b1,
                                                     e_b2, c_b1, c_w2);
    node_mma<<<nblk, ETHR, NODE_SMEM>>>(h, n_b1, n_b2, ln_g, ln_b, out);
    xnew_kernel<<<(NNODE * 3 + 255) / 256, 256>>>(x, out + NNODE * HDIM);
}